// round 1
// baseline (speedup 1.0000x reference)
#include <cuda_runtime.h>
#include <cuda_bf16.h>
#include <cstdint>

// SupCon hard-contrastive loss, restructured:
//   nce = (1/2B) * sum_i [ log( exp(2 d_ip) + (2B-2)*B'_i/A'_i ) - 2 d_ip ]
// where d_ij = dot of normalized rows, p = partner(i) = i ^ 4096,
//   A'_i = sum_{j != i,p} exp(d_ij),  B'_i = sum_{j != i,p} exp(3 d_ij)
// computed as full-row sums (GEMM + fused exp epilogue) minus analytic
// self terms (e, e^3) and the explicitly recomputed partner term.

#define NROWS 8192
#define HALFN 4096
#define DDIM  512
#define TILE  128
#define KC    32
#define NKC   (DDIM / KC)   // 16
#define PITCHB 80           // smem row pitch in bytes (80 % 128 == 80 -> conflict-free ldmatrix)

__device__ __nv_bfloat16 g_O[(size_t)NROWS * DDIM];  // normalized, bf16
__device__ float g_sumE[NROWS];                      // sum_j exp(d_ij)
__device__ float g_sumE3[NROWS];                     // sum_j exp(3 d_ij)

// ---------------------------------------------------------------- helpers
__device__ __forceinline__ void cpasync16(uint32_t saddr, const void* gaddr) {
    asm volatile("cp.async.cg.shared.global [%0], [%1], 16;\n" ::
                 "r"(saddr), "l"(gaddr));
}
__device__ __forceinline__ void cp_commit() {
    asm volatile("cp.async.commit_group;\n");
}
__device__ __forceinline__ void ldm_x4(uint32_t& r0, uint32_t& r1, uint32_t& r2,
                                       uint32_t& r3, uint32_t addr) {
    asm volatile("ldmatrix.sync.aligned.m8n8.x4.shared.b16 {%0,%1,%2,%3}, [%4];\n"
                 : "=r"(r0), "=r"(r1), "=r"(r2), "=r"(r3) : "r"(addr));
}
__device__ __forceinline__ void mma16816(float* d, const uint32_t* a,
                                         uint32_t b0, uint32_t b1) {
    asm volatile(
        "mma.sync.aligned.m16n8k16.row.col.f32.bf16.bf16.f32 "
        "{%0,%1,%2,%3}, {%4,%5,%6,%7}, {%8,%9}, {%0,%1,%2,%3};\n"
        : "+f"(d[0]), "+f"(d[1]), "+f"(d[2]), "+f"(d[3])
        : "r"(a[0]), "r"(a[1]), "r"(a[2]), "r"(a[3]), "r"(b0), "r"(b1));
}

// ------------------------------------------------- kernel 1: normalize -> bf16
__global__ __launch_bounds__(128) void normalize_kernel(const float* __restrict__ o1,
                                                        const float* __restrict__ o2) {
    const int row = blockIdx.x;
    const int tid = threadIdx.x;                       // 128 threads, 4 floats each
    const float* src = (row < HALFN) ? (o1 + (size_t)row * DDIM)
                                     : (o2 + (size_t)(row - HALFN) * DDIM);
    float4 v = reinterpret_cast<const float4*>(src)[tid];
    float ss = v.x * v.x + v.y * v.y + v.z * v.z + v.w * v.w;
#pragma unroll
    for (int o = 16; o; o >>= 1) ss += __shfl_xor_sync(0xffffffffu, ss, o);
    __shared__ float ws[4];
    if ((tid & 31) == 0) ws[tid >> 5] = ss;
    __syncthreads();
    float rn = rsqrtf(ws[0] + ws[1] + ws[2] + ws[3]);
    __nv_bfloat162* dst =
        reinterpret_cast<__nv_bfloat162*>(g_O + (size_t)row * DDIM) + tid * 2;
    dst[0] = __floats2bfloat162_rn(v.x * rn, v.y * rn);
    dst[1] = __floats2bfloat162_rn(v.z * rn, v.w * rn);
    if (tid == 0) { g_sumE[row] = 0.f; g_sumE3[row] = 0.f; }
}

// ---------------------- kernel 2: C = O*O^T tile, fused exp epilogue + row sums
__global__ __launch_bounds__(256) void gemm_exp_kernel() {
    __shared__ __nv_bfloat16 sA[2][TILE * (PITCHB / 2)];
    __shared__ __nv_bfloat16 sB[2][TILE * (PITCHB / 2)];

    const int tid  = threadIdx.x;
    const int lane = tid & 31;
    const int warp = tid >> 5;                  // 8 warps: 4 (M) x 2 (N)
    const int rowBase = blockIdx.y * TILE;
    const int colBase = blockIdx.x * TILE;
    const int m_off = (warp >> 1) * 32;
    const int n_off = (warp & 1) * 64;

    uint32_t sAu[2], sBu[2];
    sAu[0] = (uint32_t)__cvta_generic_to_shared(&sA[0][0]);
    sAu[1] = (uint32_t)__cvta_generic_to_shared(&sA[1][0]);
    sBu[0] = (uint32_t)__cvta_generic_to_shared(&sB[0][0]);
    sBu[1] = (uint32_t)__cvta_generic_to_shared(&sB[1][0]);

    // ldmatrix per-lane offsets (bytes within tile), for k-seg base 0
    const int rA   = ((lane >> 3) & 1) * 8 + (lane & 7);
    const int segA = lane >> 4;
    int aoff[2];
#pragma unroll
    for (int mt = 0; mt < 2; ++mt)
        aoff[mt] = (m_off + mt * 16 + rA) * PITCHB + segA * 16;

    const int rB   = (lane & 7) + ((lane >> 4) << 3);
    const int segB = (lane >> 3) & 1;
    int boff[4];
#pragma unroll
    for (int nq = 0; nq < 4; ++nq)
        boff[nq] = (n_off + nq * 16 + rB) * PITCHB + segB * 16;

    float acc[2][8][4];
#pragma unroll
    for (int mt = 0; mt < 2; ++mt)
#pragma unroll
        for (int nt = 0; nt < 8; ++nt)
#pragma unroll
            for (int k = 0; k < 4; ++k) acc[mt][nt][k] = 0.f;

    // chunk loader: 512 16B segs per matrix, 256 threads -> 2 each (x2 matrices)
    auto load_chunk = [&](int kc, int buf) {
#pragma unroll
        for (int j = 0; j < 2; ++j) {
            int seg = tid + j * 256;
            int r = seg >> 2, s = seg & 3;
            const __nv_bfloat16* ga =
                g_O + (size_t)(rowBase + r) * DDIM + kc * KC + s * 8;
            cpasync16(sAu[buf] + r * PITCHB + s * 16, ga);
            const __nv_bfloat16* gb =
                g_O + (size_t)(colBase + r) * DDIM + kc * KC + s * 8;
            cpasync16(sBu[buf] + r * PITCHB + s * 16, gb);
        }
    };

    load_chunk(0, 0);
    cp_commit();

    for (int kc = 0; kc < NKC; ++kc) {
        if (kc + 1 < NKC) {
            load_chunk(kc + 1, (kc + 1) & 1);
            cp_commit();
            asm volatile("cp.async.wait_group 1;\n");
        } else {
            asm volatile("cp.async.wait_group 0;\n");
        }
        __syncthreads();

        const uint32_t baseA = sAu[kc & 1];
        const uint32_t baseB = sBu[kc & 1];
#pragma unroll
        for (int ks = 0; ks < 2; ++ks) {
            uint32_t a[2][4];
#pragma unroll
            for (int mt = 0; mt < 2; ++mt)
                ldm_x4(a[mt][0], a[mt][1], a[mt][2], a[mt][3],
                       baseA + aoff[mt] + ks * 32);
            uint32_t b[4][4];
#pragma unroll
            for (int nq = 0; nq < 4; ++nq)
                ldm_x4(b[nq][0], b[nq][1], b[nq][2], b[nq][3],
                       baseB + boff[nq] + ks * 32);
#pragma unroll
            for (int mt = 0; mt < 2; ++mt)
#pragma unroll
                for (int nt = 0; nt < 8; ++nt) {
                    uint32_t b0 = b[nt >> 1][(nt & 1) * 2];
                    uint32_t b1 = b[nt >> 1][(nt & 1) * 2 + 1];
                    mma16816(acc[mt][nt], a[mt], b0, b1);
                }
        }
        __syncthreads();
    }

    // epilogue: exp, cube, row-sums
    float sE[2][2]  = {{0.f, 0.f}, {0.f, 0.f}};
    float sE3[2][2] = {{0.f, 0.f}, {0.f, 0.f}};
#pragma unroll
    for (int mt = 0; mt < 2; ++mt)
#pragma unroll
        for (int nt = 0; nt < 8; ++nt) {
            float e0 = __expf(acc[mt][nt][0]);
            float e1 = __expf(acc[mt][nt][1]);
            float e2 = __expf(acc[mt][nt][2]);
            float e3 = __expf(acc[mt][nt][3]);
            sE[mt][0]  += e0 + e1;
            sE[mt][1]  += e2 + e3;
            sE3[mt][0] += e0 * e0 * e0 + e1 * e1 * e1;
            sE3[mt][1] += e2 * e2 * e2 + e3 * e3 * e3;
        }
#pragma unroll
    for (int mt = 0; mt < 2; ++mt)
#pragma unroll
        for (int h = 0; h < 2; ++h) {
            float vE = sE[mt][h], vB = sE3[mt][h];
            vE += __shfl_xor_sync(0xffffffffu, vE, 1);
            vE += __shfl_xor_sync(0xffffffffu, vE, 2);
            vB += __shfl_xor_sync(0xffffffffu, vB, 1);
            vB += __shfl_xor_sync(0xffffffffu, vB, 2);
            if ((lane & 3) == 0) {
                int row = rowBase + m_off + mt * 16 + h * 8 + (lane >> 2);
                atomicAdd(&g_sumE[row], vE);
                atomicAdd(&g_sumE3[row], vB);
            }
        }
}

// --------------------------------- kernel 3: partner dot + per-row loss term
__global__ __launch_bounds__(128) void finalize_kernel(float* __restrict__ out) {
    const int i = blockIdx.x;
    const int p = i ^ HALFN;
    const int tid = threadIdx.x;
    const __nv_bfloat162* a =
        reinterpret_cast<const __nv_bfloat162*>(g_O + (size_t)i * DDIM);
    const __nv_bfloat162* b =
        reinterpret_cast<const __nv_bfloat162*>(g_O + (size_t)p * DDIM);
    float d = 0.f;
#pragma unroll
    for (int j = tid; j < DDIM / 2; j += 128) {
        __nv_bfloat162 x = a[j], y = b[j];
        d += __bfloat162float(x.x) * __bfloat162float(y.x) +
             __bfloat162float(x.y) * __bfloat162float(y.y);
    }
#pragma unroll
    for (int o = 16; o; o >>= 1) d += __shfl_xor_sync(0xffffffffu, d, o);
    __shared__ float ws[4];
    if ((tid & 31) == 0) ws[tid >> 5] = d;
    __syncthreads();
    if (tid == 0) {
        d = ws[0] + ws[1] + ws[2] + ws[3];
        float ed  = __expf(d);            // exp(d_ip)
        float e3d = ed * ed * ed;         // exp(3 d_ip)
        float c   = ed * ed;              // pos cost = exp(2 d_ip)
        float Ap = g_sumE[i]  - 2.71828182845904523f - ed;   // minus self, partner
        float Bp = g_sumE3[i] - 20.0855369231876677f - e3d;
        float negmean = Bp / Ap;
        float denom = c + (float)(NROWS - 2) * negmean;
        float term = logf(denom) - 2.f * d;                  // -log(c/denom)
        atomicAdd(out, term * (1.0f / (float)NROWS));
    }
}

// ------------------------------------------------------------------ launch
extern "C" void kernel_launch(void* const* d_in, const int* in_sizes, int n_in,
                              void* d_out, int out_size) {
    (void)in_sizes; (void)n_in; (void)out_size;
    // inputs: [0]=features (unused), [1]=out_1, [2]=out_2, [3]=indexes (arange)
    const float* out1 = (const float*)d_in[1];
    const float* out2 = (const float*)d_in[2];
    float* out = (float*)d_out;

    cudaMemsetAsync(out, 0, sizeof(float), 0);
    normalize_kernel<<<NROWS, 128>>>(out1, out2);
    dim3 grid(NROWS / TILE, NROWS / TILE);   // 64 x 64 tiles of 128x128
    gemm_exp_kernel<<<grid, 256>>>();
    finalize_kernel<<<NROWS, 128>>>(out);
}

// round 2
// speedup vs baseline: 1.3472x; 1.3472x over previous
#include <cuda_runtime.h>
#include <cuda_bf16.h>
#include <cstdint>

// SupCon hard-contrastive loss, restructured:
//   nce = (1/2B) * sum_i [ log( exp(2 d_ip) + (2B-2)*B'_i/A'_i ) - 2 d_ip ]
// with A'_i, B'_i full-row sums of exp(d_ij), exp(3 d_ij) minus analytic
// self/partner terms. C = O*O^T is SYMMETRIC: only the upper-triangular
// block tiles are computed; off-diagonal tiles feed row sums (bi-block rows)
// AND column sums (bj-block rows). 2080 tiles instead of 4096.

#define NROWS 8192
#define HALFN 4096
#define DDIM  512
#define TILE  128
#define KC    32
#define NKC   (DDIM / KC)   // 16
#define PITCHB 80           // smem row pitch bytes -> conflict-free ldmatrix
#define NTILES 2080         // 64*65/2 triangular tiles

__device__ __nv_bfloat16 g_O[(size_t)NROWS * DDIM];  // normalized, bf16
__device__ float g_sumE[NROWS];                      // sum_j exp(d_ij)
__device__ float g_sumE3[NROWS];                     // sum_j exp(3 d_ij)

// ---------------------------------------------------------------- helpers
__device__ __forceinline__ void cpasync16(uint32_t saddr, const void* gaddr) {
    asm volatile("cp.async.cg.shared.global [%0], [%1], 16;\n" ::
                 "r"(saddr), "l"(gaddr));
}
__device__ __forceinline__ void cp_commit() {
    asm volatile("cp.async.commit_group;\n");
}
__device__ __forceinline__ void ldm_x4(uint32_t& r0, uint32_t& r1, uint32_t& r2,
                                       uint32_t& r3, uint32_t addr) {
    asm volatile("ldmatrix.sync.aligned.m8n8.x4.shared.b16 {%0,%1,%2,%3}, [%4];\n"
                 : "=r"(r0), "=r"(r1), "=r"(r2), "=r"(r3) : "r"(addr));
}
__device__ __forceinline__ void mma16816(float* d, const uint32_t* a,
                                         uint32_t b0, uint32_t b1) {
    asm volatile(
        "mma.sync.aligned.m16n8k16.row.col.f32.bf16.bf16.f32 "
        "{%0,%1,%2,%3}, {%4,%5,%6,%7}, {%8,%9}, {%0,%1,%2,%3};\n"
        : "+f"(d[0]), "+f"(d[1]), "+f"(d[2]), "+f"(d[3])
        : "r"(a[0]), "r"(a[1]), "r"(a[2]), "r"(a[3]), "r"(b0), "r"(b1));
}

// ------------------------------------------------- kernel 1: normalize -> bf16
__global__ __launch_bounds__(128) void normalize_kernel(const float* __restrict__ o1,
                                                        const float* __restrict__ o2) {
    const int row = blockIdx.x;
    const int tid = threadIdx.x;                       // 128 threads, 4 floats each
    const float* src = (row < HALFN) ? (o1 + (size_t)row * DDIM)
                                     : (o2 + (size_t)(row - HALFN) * DDIM);
    float4 v = reinterpret_cast<const float4*>(src)[tid];
    float ss = v.x * v.x + v.y * v.y + v.z * v.z + v.w * v.w;
#pragma unroll
    for (int o = 16; o; o >>= 1) ss += __shfl_xor_sync(0xffffffffu, ss, o);
    __shared__ float ws[4];
    if ((tid & 31) == 0) ws[tid >> 5] = ss;
    __syncthreads();
    float rn = rsqrtf(ws[0] + ws[1] + ws[2] + ws[3]);
    __nv_bfloat162* dst =
        reinterpret_cast<__nv_bfloat162*>(g_O + (size_t)row * DDIM) + tid * 2;
    dst[0] = __floats2bfloat162_rn(v.x * rn, v.y * rn);
    dst[1] = __floats2bfloat162_rn(v.z * rn, v.w * rn);
    if (tid == 0) { g_sumE[row] = 0.f; g_sumE3[row] = 0.f; }
}

// ---------------- kernel 2: triangular C = O*O^T tiles, fused exp + row/col sums
__global__ __launch_bounds__(256) void gemm_exp_kernel() {
    __shared__ __nv_bfloat16 sA[2][TILE * (PITCHB / 2)];
    __shared__ __nv_bfloat16 sB[2][TILE * (PITCHB / 2)];

    // decode triangular tile index: t = bj*(bj+1)/2 + bi, bi <= bj
    const int t = blockIdx.x;
    int bj = (int)((sqrtf(8.0f * (float)t + 1.0f) - 1.0f) * 0.5f);
    while ((bj + 1) * (bj + 2) / 2 <= t) ++bj;
    while (bj * (bj + 1) / 2 > t) --bj;
    const int bi = t - bj * (bj + 1) / 2;
    const bool diag = (bi == bj);

    const int tid  = threadIdx.x;
    const int lane = tid & 31;
    const int warp = tid >> 5;                  // 8 warps: 4 (M) x 2 (N)
    const int rowBase = bi * TILE;
    const int colBase = bj * TILE;
    const int m_off = (warp >> 1) * 32;
    const int n_off = (warp & 1) * 64;

    uint32_t sAu[2], sBu[2];
    sAu[0] = (uint32_t)__cvta_generic_to_shared(&sA[0][0]);
    sAu[1] = (uint32_t)__cvta_generic_to_shared(&sA[1][0]);
    sBu[0] = (uint32_t)__cvta_generic_to_shared(&sB[0][0]);
    sBu[1] = (uint32_t)__cvta_generic_to_shared(&sB[1][0]);

    // ldmatrix per-lane offsets (bytes within tile)
    const int rA   = ((lane >> 3) & 1) * 8 + (lane & 7);
    const int segA = lane >> 4;
    int aoff[2];
#pragma unroll
    for (int mt = 0; mt < 2; ++mt)
        aoff[mt] = (m_off + mt * 16 + rA) * PITCHB + segA * 16;

    const int rB   = (lane & 7) + ((lane >> 4) << 3);
    const int segB = (lane >> 3) & 1;
    int boff[4];
#pragma unroll
    for (int nq = 0; nq < 4; ++nq)
        boff[nq] = (n_off + nq * 16 + rB) * PITCHB + segB * 16;

    float acc[2][8][4];
#pragma unroll
    for (int mt = 0; mt < 2; ++mt)
#pragma unroll
        for (int nt = 0; nt < 8; ++nt)
#pragma unroll
            for (int k = 0; k < 4; ++k) acc[mt][nt][k] = 0.f;

    // chunk loader: 512 16B segs per matrix, 256 threads -> 2 each (x2 matrices)
    auto load_chunk = [&](int kc, int buf) {
#pragma unroll
        for (int j = 0; j < 2; ++j) {
            int seg = tid + j * 256;
            int r = seg >> 2, s = seg & 3;
            const __nv_bfloat16* ga =
                g_O + (size_t)(rowBase + r) * DDIM + kc * KC + s * 8;
            cpasync16(sAu[buf] + r * PITCHB + s * 16, ga);
            const __nv_bfloat16* gb =
                g_O + (size_t)(colBase + r) * DDIM + kc * KC + s * 8;
            cpasync16(sBu[buf] + r * PITCHB + s * 16, gb);
        }
    };

    load_chunk(0, 0);
    cp_commit();

    for (int kc = 0; kc < NKC; ++kc) {
        if (kc + 1 < NKC) {
            load_chunk(kc + 1, (kc + 1) & 1);
            cp_commit();
            asm volatile("cp.async.wait_group 1;\n");
        } else {
            asm volatile("cp.async.wait_group 0;\n");
        }
        __syncthreads();

        const uint32_t baseA = sAu[kc & 1];
        const uint32_t baseB = sBu[kc & 1];
#pragma unroll
        for (int ks = 0; ks < 2; ++ks) {
            uint32_t a[2][4];
#pragma unroll
            for (int mt = 0; mt < 2; ++mt)
                ldm_x4(a[mt][0], a[mt][1], a[mt][2], a[mt][3],
                       baseA + aoff[mt] + ks * 32);
            uint32_t b[4][4];
#pragma unroll
            for (int nq = 0; nq < 4; ++nq)
                ldm_x4(b[nq][0], b[nq][1], b[nq][2], b[nq][3],
                       baseB + boff[nq] + ks * 32);
#pragma unroll
            for (int mt = 0; mt < 2; ++mt)
#pragma unroll
                for (int nt = 0; nt < 8; ++nt) {
                    uint32_t b0 = b[nt >> 1][(nt & 1) * 2];
                    uint32_t b1 = b[nt >> 1][(nt & 1) * 2 + 1];
                    mma16816(acc[mt][nt], a[mt], b0, b1);
                }
        }
        __syncthreads();
    }

    // ---- epilogue pass 1: exp in-place, row sums (rows of bi-block) ----
    float sE[2][2]  = {{0.f, 0.f}, {0.f, 0.f}};
    float sE3[2][2] = {{0.f, 0.f}, {0.f, 0.f}};
#pragma unroll
    for (int mt = 0; mt < 2; ++mt)
#pragma unroll
        for (int nt = 0; nt < 8; ++nt) {
            float e0 = __expf(acc[mt][nt][0]);
            float e1 = __expf(acc[mt][nt][1]);
            float e2 = __expf(acc[mt][nt][2]);
            float e3 = __expf(acc[mt][nt][3]);
            acc[mt][nt][0] = e0; acc[mt][nt][1] = e1;
            acc[mt][nt][2] = e2; acc[mt][nt][3] = e3;
            sE[mt][0]  += e0 + e1;
            sE[mt][1]  += e2 + e3;
            sE3[mt][0] += e0 * e0 * e0 + e1 * e1 * e1;
            sE3[mt][1] += e2 * e2 * e2 + e3 * e3 * e3;
        }
#pragma unroll
    for (int mt = 0; mt < 2; ++mt)
#pragma unroll
        for (int h = 0; h < 2; ++h) {
            float vE = sE[mt][h], vB = sE3[mt][h];
            vE += __shfl_xor_sync(0xffffffffu, vE, 1);
            vE += __shfl_xor_sync(0xffffffffu, vE, 2);
            vB += __shfl_xor_sync(0xffffffffu, vB, 1);
            vB += __shfl_xor_sync(0xffffffffu, vB, 2);
            if ((lane & 3) == 0) {
                int row = rowBase + m_off + mt * 16 + h * 8 + (lane >> 2);
                atomicAdd(&g_sumE[row], vE);
                atomicAdd(&g_sumE3[row], vB);
            }
        }

    // ---- epilogue pass 2 (off-diag only): column sums -> rows of bj-block ----
    // acc now holds e = exp(d). Column sum over the tile's 128 M-rows equals
    // the symmetric contribution to row (colBase + n)'s sums.
    if (!diag) {
#pragma unroll
        for (int nt = 0; nt < 8; ++nt) {
            // each lane owns cols 2*(lane&3), 2*(lane&3)+1 of this n8 tile;
            // rows lane>>2 and (lane>>2)+8, for both mt tiles.
            float ce0 = 0.f, ce1 = 0.f, cb0 = 0.f, cb1 = 0.f;
#pragma unroll
            for (int mt = 0; mt < 2; ++mt) {
                float e0 = acc[mt][nt][0], e1 = acc[mt][nt][1];
                float e2 = acc[mt][nt][2], e3 = acc[mt][nt][3];
                ce0 += e0 + e2;
                ce1 += e1 + e3;
                cb0 += e0 * e0 * e0 + e2 * e2 * e2;
                cb1 += e1 * e1 * e1 + e3 * e3 * e3;
            }
            // reduce across the 8 row-lane groups (bits 2..4 of lane)
#pragma unroll
            for (int o = 4; o <= 16; o <<= 1) {
                ce0 += __shfl_xor_sync(0xffffffffu, ce0, o);
                ce1 += __shfl_xor_sync(0xffffffffu, ce1, o);
                cb0 += __shfl_xor_sync(0xffffffffu, cb0, o);
                cb1 += __shfl_xor_sync(0xffffffffu, cb1, o);
            }
            if (lane < 4) {
                int col = colBase + n_off + (nt >> 1) * 16 + (nt & 1) * 8 + 2 * lane;
                atomicAdd(&g_sumE[col],      ce0);
                atomicAdd(&g_sumE[col + 1],  ce1);
                atomicAdd(&g_sumE3[col],     cb0);
                atomicAdd(&g_sumE3[col + 1], cb1);
            }
        }
    }
}

// --------------------------------- kernel 3: partner dot + per-row loss term
__global__ __launch_bounds__(128) void finalize_kernel(float* __restrict__ out) {
    const int i = blockIdx.x;
    const int p = i ^ HALFN;
    const int tid = threadIdx.x;
    const __nv_bfloat162* a =
        reinterpret_cast<const __nv_bfloat162*>(g_O + (size_t)i * DDIM);
    const __nv_bfloat162* b =
        reinterpret_cast<const __nv_bfloat162*>(g_O + (size_t)p * DDIM);
    float d = 0.f;
#pragma unroll
    for (int j = tid; j < DDIM / 2; j += 128) {
        __nv_bfloat162 x = a[j], y = b[j];
        d += __bfloat162float(x.x) * __bfloat162float(y.x) +
             __bfloat162float(x.y) * __bfloat162float(y.y);
    }
#pragma unroll
    for (int o = 16; o; o >>= 1) d += __shfl_xor_sync(0xffffffffu, d, o);
    __shared__ float ws[4];
    if ((tid & 31) == 0) ws[tid >> 5] = d;
    __syncthreads();
    if (tid == 0) {
        d = ws[0] + ws[1] + ws[2] + ws[3];
        float ed  = __expf(d);            // exp(d_ip)
        float e3d = ed * ed * ed;         // exp(3 d_ip)
        float c   = ed * ed;              // pos cost = exp(2 d_ip)
        float Ap = g_sumE[i]  - 2.71828182845904523f - ed;   // minus self, partner
        float Bp = g_sumE3[i] - 20.0855369231876677f - e3d;
        float negmean = Bp / Ap;
        float denom = c + (float)(NROWS - 2) * negmean;
        float term = logf(denom) - 2.f * d;                  // -log(c/denom)
        atomicAdd(out, term * (1.0f / (float)NROWS));
    }
}

// ------------------------------------------------------------------ launch
extern "C" void kernel_launch(void* const* d_in, const int* in_sizes, int n_in,
                              void* d_out, int out_size) {
    (void)in_sizes; (void)n_in; (void)out_size;
    // inputs: [0]=features (unused), [1]=out_1, [2]=out_2, [3]=indexes (arange)
    const float* out1 = (const float*)d_in[1];
    const float* out2 = (const float*)d_in[2];
    float* out = (float*)d_out;

    cudaMemsetAsync(out, 0, sizeof(float), 0);
    normalize_kernel<<<NROWS, 128>>>(out1, out2);
    gemm_exp_kernel<<<NTILES, 256>>>();
    finalize_kernel<<<NROWS, 128>>>(out);
}